// round 10
// baseline (speedup 1.0000x reference)
#include <cuda_runtime.h>
#include <cuda_fp16.h>
#include <cstdint>

#define DV 128
#define NT 512
#define NWORK 4096      // 32 token-tiles * 128 i-values

// smem offsets in uint2 units
#define SLAB_STRIDE 132                 // uint2 per (c,q)-row: 128 + 4 pad
#define SLAB_U2     (32 * SLAB_STRIDE)  // 4224 uint2 per stage
#define NSTAGE      3
#define OFF_ARGP    (NSTAGE * SLAB_U2)  // 12672
#define ARGP_STRIDE 36                  // uint2 per token row: 32 + 4 pad
#define SM_U2       (OFF_ARGP + 128 * ARGP_STRIDE)  // 17280
#define SM_BYTES    (SM_U2 * 8)         // 138240

// C pair-packed: g_CP[i*4096 + c*512 + q*128 + z] =
//   { half2(C[i][16c+2q][z],   C[i][16c+2q+1][z]),
//     half2(C[i][16c+2q+8][z], C[i][16c+2q+9][z]) }
__device__ uint2 g_CP[DV * 4096];

__device__ __forceinline__ uint32_t smem_u32(const void* p) {
    uint32_t a;
    asm("{ .reg .u64 t; cvta.to.shared.u64 t, %1; cvt.u32.u64 %0, t; }"
        : "=r"(a) : "l"(p));
    return a;
}
__device__ __forceinline__ uint32_t pack_f16x2(float hi, float lo) {
    uint32_t r;
    asm("cvt.rn.f16x2.f32 %0, %1, %2;" : "=r"(r) : "f"(hi), "f"(lo));
    return r;
}
__device__ __forceinline__ uint32_t hmul2(uint32_t a, uint32_t b) {
    uint32_t r;
    asm("mul.rn.f16x2 %0, %1, %2;" : "=r"(r) : "r"(a), "r"(b));
    return r;
}
__device__ __forceinline__ void cp16(uint32_t dst, const void* src) {
    asm volatile("cp.async.cg.shared.global [%0], [%1], 16;"
                 :: "r"(dst), "l"(src) : "memory");
}
#define CP_COMMIT() asm volatile("cp.async.commit_group;" ::: "memory")
#define CP_WAIT(n)  asm volatile("cp.async.wait_group %0;" :: "n"(n) : "memory")

__device__ __forceinline__ void mma_f16(float* c, const uint32_t* a,
                                        uint32_t b0, uint32_t b1) {
    asm volatile(
        "mma.sync.aligned.m16n8k16.row.col.f32.f16.f16.f32 "
        "{%0,%1,%2,%3}, {%4,%5,%6,%7}, {%8,%9}, {%0,%1,%2,%3};"
        : "+f"(c[0]), "+f"(c[1]), "+f"(c[2]), "+f"(c[3])
        : "r"(a[0]), "r"(a[1]), "r"(a[2]), "r"(a[3]), "r"(b0), "r"(b1));
}

// ---- pack C -> fp16 pair-of-pairs layout; also zero the output ----
__global__ void __launch_bounds__(256) pack_c(const float* __restrict__ C,
                                              float* __restrict__ out) {
    unsigned idx = blockIdx.x * 256 + threadIdx.x;   // 524288 threads
    out[idx] = 0.f;                                  // out has 524288 floats
    int z = (int)(idx & 127);
    int q = (int)((idx >> 7) & 3);
    int c = (int)((idx >> 9) & 7);
    int i = (int)(idx >> 12);
    const float* base = C + ((size_t)i * DV + 16 * c + 2 * q) * DV + z;
    float v0 = base[0];
    float v1 = base[DV];
    float v8 = base[8 * DV];
    float v9 = base[9 * DV];
    uint2 r;
    r.x = pack_f16x2(v1, v0);
    r.y = pack_f16x2(v9, v8);
    g_CP[idx] = r;
}

__global__ void __launch_bounds__(NT, 1)
cooc_mma(const float* __restrict__ fa, float* __restrict__ out) {
    extern __shared__ uint2 smu[];
    const int tid  = threadIdx.x;
    const int warp = tid >> 5, lane = tid & 31;
    const int g = lane >> 2, q = lane & 3;
    const int mbase = (warp >> 2) * 32;   // warp-row tile (32 tokens)
    const int nbase = (warp & 3) * 32;    // warp-col tile (32 z)

    uint2* argp = smu + OFF_ARGP;
    uint32_t* arg32 = (uint32_t*)argp;
    const uint32_t sb = smem_u32(smu);

    // stream-K range for this CTA
    const unsigned nb = gridDim.x;
    const unsigned w0 = (unsigned)((unsigned long long)blockIdx.x * NWORK / nb);
    const unsigned w1 = (unsigned)((unsigned long long)(blockIdx.x + 1) * NWORK / nb);

    // ---- arg restage: f32 LDG -> pair-packed half2 uint2 [t][c*4+q] ----
    auto stage_arg = [&](int tile) {
        const int tok0 = tile * 128;
        #pragma unroll 4
        for (int idx = tid; idx < 128 * 32; idx += NT) {
            int t = idx >> 5, c4 = idx & 31;
            float4 v = *(const float4*)(fa + (size_t)(tok0 + t) * 256 + DV + c4 * 4);
            int cc = c4 >> 2;            // chunk
            int ra = (2 * c4) & 7;       // r of first j2
            uint32_t w0v = pack_f16x2(v.y, v.x);
            uint32_t w1v = pack_f16x2(v.w, v.z);
            int ia = 2 * (t * ARGP_STRIDE + cc * 4 + (ra & 3)) + (ra >> 2);
            int rb = ra + 1;
            int ib = 2 * (t * ARGP_STRIDE + cc * 4 + (rb & 3)) + (rb >> 2);
            arg32[ia] = w0v;
            arg32[ib] = w1v;
        }
    };
    // ---- cp.async slab stager: g_CP[i] (32 rows x 128 uint2) -> stage s ----
    auto stage_slab = [&](int i, int stg) {
        const uint2* src = g_CP + ((size_t)i << 12);
        uint32_t dstb = sb + (unsigned)stg * SLAB_U2 * 8;
        #pragma unroll
        for (int k = 0; k < 4; k++) {
            int c = tid + k * NT;          // 16B chunk id, 0..2047
            int row = c >> 6, col = c & 63;
            cp16(dstb + (row * SLAB_STRIDE + col * 2) * 8,
                 src + row * 128 + col * 2);
        }
    };
    // ---- func column prefetch for work unit w (4 regs) ----
    auto load_func = [&](unsigned w, float* fr) {
        const int tk = (int)(w >> 7) * 128;
        const int i  = (int)(w & 127);
        #pragma unroll
        for (int s = 0; s < 4; s++)
            fr[s] = fa[(size_t)(tk + mbase + g + 8 * s) * 256 + i];
    };

    float acc[2][4][4];
    #pragma unroll
    for (int mt = 0; mt < 2; mt++)
        #pragma unroll
        for (int nt = 0; nt < 4; nt++)
            #pragma unroll
            for (int k = 0; k < 4; k++) acc[mt][nt][k] = 0.f;

    auto flush = [&](int tile) {
        const int tok0 = tile * 128;
        #pragma unroll
        for (int mt = 0; mt < 2; mt++) {
            int r0 = tok0 + mbase + mt * 16 + g;
            #pragma unroll
            for (int nt = 0; nt < 4; nt++) {
                int col = nbase + nt * 8 + 2 * q;
                float* p0 = out + (size_t)r0 * DV + col;
                atomicAdd(p0,              acc[mt][nt][0]);
                atomicAdd(p0 + 1,          acc[mt][nt][1]);
                atomicAdd(p0 + 8 * DV,     acc[mt][nt][2]);
                atomicAdd(p0 + 8 * DV + 1, acc[mt][nt][3]);
                acc[mt][nt][0] = acc[mt][nt][1] = 0.f;
                acc[mt][nt][2] = acc[mt][nt][3] = 0.f;
            }
        }
    };

    int cur_tile = (int)(w0 >> 7);
    stage_arg(cur_tile);
    stage_slab((int)(w0 & 127), 0);
    CP_COMMIT();
    float fr_next[4];
    load_func(w0, fr_next);
    __syncthreads();   // argp for first tile visible

    uint32_t aF[2][2][4];    // [buf][mt][frag]
    uint32_t bF[2][4][2];    // [buf][nt][frag]

    // per-warp fragment base pointers (valid for current tile / stage)
    const uint2* abase0 = argp + (mbase + g) * ARGP_STRIDE + q;

    for (unsigned w = w0; w < w1; ++w) {
        const int stg = (int)((w - w0) % 3);
        const int tile = (int)(w >> 7);
        if (tile != cur_tile) {      // uniform branch; <=1 per CTA
            flush(cur_tile);
            cur_tile = tile;
            __syncthreads();         // all warps done reading old argp
            stage_arg(cur_tile);
        }
        if (w + 1 < w1) {
            stage_slab((int)((w + 1) & 127), (int)((w - w0 + 1) % 3));
            CP_COMMIT();
        }

        float fr_cur[4];
        #pragma unroll
        for (int s = 0; s < 4; s++) fr_cur[s] = fr_next[s];
        if (w + 1 < w1) load_func(w + 1, fr_next);

        if (w + 1 < w1) CP_WAIT(1); else CP_WAIT(0);
        __syncthreads();             // slab stage stg (and argp) visible

        const uint2* bbase = smu + stg * SLAB_U2 + q * SLAB_STRIDE + nbase + g;

        uint32_t fr2[4];
        #pragma unroll
        for (int s = 0; s < 4; s++) fr2[s] = pack_f16x2(fr_cur[s], fr_cur[s]);

        // fragment loader for k16-chunk c into buffer fb (all LDS.64)
        auto load_chunk = [&](int c, int fb) {
            const uint2* brow = bbase + c * 4 * SLAB_STRIDE;
            #pragma unroll
            for (int nt = 0; nt < 4; nt++) {
                uint2 v = brow[nt * 8];
                bF[fb][nt][0] = v.x;
                bF[fb][nt][1] = v.y;
            }
            const uint2* ap = abase0 + c * 4;
            #pragma unroll
            for (int s = 0; s < 4; s++) {
                uint2 av = ap[s * 8 * ARGP_STRIDE];
                aF[fb][s >> 1][(s & 1) ? 1 : 0] = hmul2(fr2[s], av.x);
                aF[fb][s >> 1][(s & 1) ? 3 : 2] = hmul2(fr2[s], av.y);
            }
        };

        load_chunk(0, 0);
        #pragma unroll
        for (int c = 0; c < 8; c++) {
            const int cur = c & 1, nxt = cur ^ 1;
            if (c < 7) load_chunk(c + 1, nxt);
            #pragma unroll
            for (int nt = 0; nt < 4; nt++) {
                mma_f16(acc[0][nt], aF[cur][0], bF[cur][nt][0], bF[cur][nt][1]);
                mma_f16(acc[1][nt], aF[cur][1], bF[cur][nt][0], bF[cur][nt][1]);
            }
        }
        // no trailing barrier: 3-stage ring keeps writers off live stages
    }
    flush(cur_tile);
}

extern "C" void kernel_launch(void* const* d_in, const int* in_sizes, int n_in,
                              void* d_out, int out_size) {
    const float* fa = (const float*)d_in[0];   // (4,1024,256)
    const float* Cm = (const float*)d_in[1];   // (128,128,128)
    if (n_in >= 2 && in_sizes[0] > in_sizes[1]) {
        const float* t = fa; fa = Cm; Cm = t;
    }
    float* out = (float*)d_out;

    int nsm = 148;
    cudaDeviceGetAttribute(&nsm, cudaDevAttrMultiProcessorCount, 0);
    if (nsm <= 0 || nsm > NWORK) nsm = 148;

    cudaFuncSetAttribute(cooc_mma, cudaFuncAttributeMaxDynamicSharedMemorySize,
                         SM_BYTES);
    pack_c<<<2048, 256>>>(Cm, out);   // also zeroes out
    cooc_mma<<<nsm, NT, SM_BYTES>>>(fa, out);
}

// round 11
// speedup vs baseline: 1.1011x; 1.1011x over previous
#include <cuda_runtime.h>
#include <cuda_fp16.h>
#include <cstdint>

#define DV 128
#define NT 256
#define NWORK 4096      // 32 token-tiles * 128 i-values

// smem offsets in uint2 units
#define SLAB_STRIDE 132                 // uint2 per (c,q)-row: 128 + 4 pad
#define SLAB_U2     (32 * SLAB_STRIDE)  // 4224 uint2 per stage
#define NSTAGE      3
#define OFF_ARGP    (NSTAGE * SLAB_U2)  // 12672
#define ARGP_STRIDE 36                  // uint2 per token row: 32 + 4 pad
#define SM_U2       (OFF_ARGP + 128 * ARGP_STRIDE)  // 17280
#define SM_BYTES    (SM_U2 * 8)         // 138240

// C pair-packed: g_CP[i*4096 + c*512 + q*128 + z] =
//   { half2(C[i][16c+2q][z],   C[i][16c+2q+1][z]),
//     half2(C[i][16c+2q+8][z], C[i][16c+2q+9][z]) }
__device__ uint2 g_CP[DV * 4096];

__device__ __forceinline__ uint32_t smem_u32(const void* p) {
    uint32_t a;
    asm("{ .reg .u64 t; cvta.to.shared.u64 t, %1; cvt.u32.u64 %0, t; }"
        : "=r"(a) : "l"(p));
    return a;
}
__device__ __forceinline__ uint32_t pack_f16x2(float hi, float lo) {
    uint32_t r;
    asm("cvt.rn.f16x2.f32 %0, %1, %2;" : "=r"(r) : "f"(hi), "f"(lo));
    return r;
}
__device__ __forceinline__ uint32_t hmul2(uint32_t a, uint32_t b) {
    uint32_t r;
    asm("mul.rn.f16x2 %0, %1, %2;" : "=r"(r) : "r"(a), "r"(b));
    return r;
}
__device__ __forceinline__ void cp16(uint32_t dst, const void* src) {
    asm volatile("cp.async.cg.shared.global [%0], [%1], 16;"
                 :: "r"(dst), "l"(src) : "memory");
}
#define CP_COMMIT() asm volatile("cp.async.commit_group;" ::: "memory")
#define CP_WAIT(n)  asm volatile("cp.async.wait_group %0;" :: "n"(n) : "memory")

__device__ __forceinline__ void mma_f16(float* c, const uint32_t* a,
                                        uint32_t b0, uint32_t b1) {
    asm volatile(
        "mma.sync.aligned.m16n8k16.row.col.f32.f16.f16.f32 "
        "{%0,%1,%2,%3}, {%4,%5,%6,%7}, {%8,%9}, {%0,%1,%2,%3};"
        : "+f"(c[0]), "+f"(c[1]), "+f"(c[2]), "+f"(c[3])
        : "r"(a[0]), "r"(a[1]), "r"(a[2]), "r"(a[3]), "r"(b0), "r"(b1));
}

// ---- pack C -> fp16 pair-of-pairs layout; also zero the output ----
__global__ void __launch_bounds__(256) pack_c(const float* __restrict__ C,
                                              float* __restrict__ out) {
    unsigned idx = blockIdx.x * 256 + threadIdx.x;   // 524288 threads
    out[idx] = 0.f;                                  // out has 524288 floats
    int z = (int)(idx & 127);
    int q = (int)((idx >> 7) & 3);
    int c = (int)((idx >> 9) & 7);
    int i = (int)(idx >> 12);
    const float* base = C + ((size_t)i * DV + 16 * c + 2 * q) * DV + z;
    float v0 = base[0];
    float v1 = base[DV];
    float v8 = base[8 * DV];
    float v9 = base[9 * DV];
    uint2 r;
    r.x = pack_f16x2(v1, v0);
    r.y = pack_f16x2(v9, v8);
    g_CP[idx] = r;
}

__global__ void __launch_bounds__(NT, 1)
cooc_mma(const float* __restrict__ fa, float* __restrict__ out) {
    extern __shared__ uint2 smu[];
    const int tid  = threadIdx.x;
    const int warp = tid >> 5, lane = tid & 31;
    const int g = lane >> 2, q = lane & 3;
    const int mbase = (warp >> 1) * 32;   // warp-row tile (32 tokens)
    const int nbase = (warp & 1) * 64;    // warp-col tile (64 z)

    uint2* argp = smu + OFF_ARGP;
    uint32_t* arg32 = (uint32_t*)argp;
    const uint32_t sb = smem_u32(smu);

    // stream-K range for this CTA
    const unsigned nb = gridDim.x;
    const unsigned w0 = (unsigned)((unsigned long long)blockIdx.x * NWORK / nb);
    const unsigned w1 = (unsigned)((unsigned long long)(blockIdx.x + 1) * NWORK / nb);

    // ---- arg restage: f32 LDG -> pair-packed half2 uint2 [t][c*4+q] ----
    auto stage_arg = [&](int tile) {
        const int tok0 = tile * 128;
        #pragma unroll 4
        for (int idx = tid; idx < 128 * 32; idx += NT) {
            int t = idx >> 5, c4 = idx & 31;
            float4 v = *(const float4*)(fa + (size_t)(tok0 + t) * 256 + DV + c4 * 4);
            int cc = c4 >> 2;            // chunk
            int ra = (2 * c4) & 7;       // r of first j2
            uint32_t w0v = pack_f16x2(v.y, v.x);
            uint32_t w1v = pack_f16x2(v.w, v.z);
            int ia = 2 * (t * ARGP_STRIDE + cc * 4 + (ra & 3)) + (ra >> 2);
            int rb = ra + 1;
            int ib = 2 * (t * ARGP_STRIDE + cc * 4 + (rb & 3)) + (rb >> 2);
            arg32[ia] = w0v;
            arg32[ib] = w1v;
        }
    };
    // ---- cp.async slab stager: g_CP[i] (32 rows x 128 uint2) -> stage stg ----
    auto stage_slab = [&](int i, int stg) {
        const uint2* src = g_CP + ((size_t)i << 12);
        uint32_t dstb = sb + (unsigned)stg * SLAB_U2 * 8;
        #pragma unroll
        for (int k = 0; k < 8; k++) {
            int c = tid + k * NT;          // 16B chunk id, 0..2047
            int row = c >> 6, col = c & 63;
            cp16(dstb + (row * SLAB_STRIDE + col * 2) * 8,
                 src + row * 128 + col * 2);
        }
    };
    // ---- func column prefetch for work unit w (4 regs) ----
    auto load_func = [&](unsigned w, float* fr) {
        const int tk = (int)(w >> 7) * 128;
        const int i  = (int)(w & 127);
        #pragma unroll
        for (int s = 0; s < 4; s++)
            fr[s] = fa[(size_t)(tk + mbase + g + 8 * s) * 256 + i];
    };

    float acc[2][8][4];
    #pragma unroll
    for (int mt = 0; mt < 2; mt++)
        #pragma unroll
        for (int nt = 0; nt < 8; nt++)
            #pragma unroll
            for (int k = 0; k < 4; k++) acc[mt][nt][k] = 0.f;

    auto flush = [&](int tile) {
        const int tok0 = tile * 128;
        #pragma unroll
        for (int mt = 0; mt < 2; mt++) {
            int r0 = tok0 + mbase + mt * 16 + g;
            #pragma unroll
            for (int nt = 0; nt < 8; nt++) {
                int col = nbase + nt * 8 + 2 * q;
                float* p0 = out + (size_t)r0 * DV + col;
                atomicAdd(p0,              acc[mt][nt][0]);
                atomicAdd(p0 + 1,          acc[mt][nt][1]);
                atomicAdd(p0 + 8 * DV,     acc[mt][nt][2]);
                atomicAdd(p0 + 8 * DV + 1, acc[mt][nt][3]);
                acc[mt][nt][0] = acc[mt][nt][1] = 0.f;
                acc[mt][nt][2] = acc[mt][nt][3] = 0.f;
            }
        }
    };

    int cur_tile = (int)(w0 >> 7);
    stage_arg(cur_tile);
    stage_slab((int)(w0 & 127), 0);
    CP_COMMIT();
    float fr_next[4];
    load_func(w0, fr_next);

    uint32_t aF[2][2][4];    // [buf][mt][frag]
    uint32_t bF[2][8][2];    // [buf][nt][frag]

    for (unsigned w = w0; w < w1; ++w) {
        const int stg = (int)((w - w0) % 3);
        const int tile = (int)(w >> 7);
        if (tile != cur_tile) {      // uniform branch; <=1 per CTA typically
            flush(cur_tile);
            cur_tile = tile;
            __syncthreads();         // all warps done reading old argp
            stage_arg(cur_tile);
        }
        if (w + 1 < w1) {
            stage_slab((int)((w + 1) & 127), (int)((w - w0 + 1) % 3));
            CP_COMMIT();
        }

        float fr_cur[4];
        #pragma unroll
        for (int s = 0; s < 4; s++) fr_cur[s] = fr_next[s];
        if (w + 1 < w1) load_func(w + 1, fr_next);

        if (w + 1 < w1) CP_WAIT(1); else CP_WAIT(0);
        __syncthreads();             // stage stg (and argp on first w) visible

        const uint2* slab = smu + stg * SLAB_U2;

        uint32_t fr2[4];
        #pragma unroll
        for (int s = 0; s < 4; s++) fr2[s] = pack_f16x2(fr_cur[s], fr_cur[s]);

        // fragment loader for k16-chunk c into buffer fb (all LDS.64)
        auto load_chunk = [&](int c, int fb) {
            const uint2* brow = slab + (c * 4 + q) * SLAB_STRIDE + nbase + g;
            #pragma unroll
            for (int nt = 0; nt < 8; nt++) {
                uint2 v = brow[nt * 8];
                bF[fb][nt][0] = v.x;
                bF[fb][nt][1] = v.y;
            }
            #pragma unroll
            for (int s = 0; s < 4; s++) {
                uint2 av = argp[(mbase + g + 8 * s) * ARGP_STRIDE + c * 4 + q];
                aF[fb][s >> 1][(s & 1) ? 1 : 0] = hmul2(fr2[s], av.x);
                aF[fb][s >> 1][(s & 1) ? 3 : 2] = hmul2(fr2[s], av.y);
            }
        };

        load_chunk(0, 0);
        #pragma unroll
        for (int c = 0; c < 8; c++) {
            const int cur = c & 1, nxt = cur ^ 1;
            if (c < 7) load_chunk(c + 1, nxt);
            #pragma unroll
            for (int nt = 0; nt < 8; nt++) {
                mma_f16(acc[0][nt], aF[cur][0], bF[cur][nt][0], bF[cur][nt][1]);
                mma_f16(acc[1][nt], aF[cur][1], bF[cur][nt][0], bF[cur][nt][1]);
            }
        }
        // no trailing barrier: 3-stage ring keeps writers off live stages
    }
    flush(cur_tile);
}

extern "C" void kernel_launch(void* const* d_in, const int* in_sizes, int n_in,
                              void* d_out, int out_size) {
    const float* fa = (const float*)d_in[0];   // (4,1024,256)
    const float* Cm = (const float*)d_in[1];   // (128,128,128)
    if (n_in >= 2 && in_sizes[0] > in_sizes[1]) {
        const float* t = fa; fa = Cm; Cm = t;
    }
    float* out = (float*)d_out;

    int nsm = 148;
    cudaDeviceGetAttribute(&nsm, cudaDevAttrMultiProcessorCount, 0);
    if (nsm <= 0 || nsm > NWORK) nsm = 148;

    cudaFuncSetAttribute(cooc_mma, cudaFuncAttributeMaxDynamicSharedMemorySize,
                         SM_BYTES);
    pack_c<<<2048, 256>>>(Cm, out);   // also zeroes out
    cooc_mma<<<nsm, NT, SM_BYTES>>>(fa, out);
}

// round 12
// speedup vs baseline: 1.1090x; 1.0071x over previous
#include <cuda_runtime.h>
#include <cuda_fp16.h>
#include <cstdint>

#define DV 128
#define NT 256
#define NWORK 4096      // 32 token-tiles * 128 i-values

// smem offsets in uint2 units
#define SLAB_STRIDE 132                 // uint2 per (c,q)-row: 128 + 4 pad
#define SLAB_U2     (32 * SLAB_STRIDE)  // 4224 uint2 per stage
#define NSTAGE      4                   // 2 pairs
#define OFF_ARGP    (NSTAGE * SLAB_U2)  // 16896
#define ARGP_STRIDE 36                  // uint2 per token row: 32 + 4 pad
#define SM_U2       (OFF_ARGP + 128 * ARGP_STRIDE)  // 21504
#define SM_BYTES    (SM_U2 * 8)         // 172032

// C pair-packed: g_CP[i*4096 + c*512 + q*128 + z] =
//   { half2(C[i][16c+2q][z],   C[i][16c+2q+1][z]),
//     half2(C[i][16c+2q+8][z], C[i][16c+2q+9][z]) }
__device__ uint2 g_CP[DV * 4096];

__device__ __forceinline__ uint32_t smem_u32(const void* p) {
    uint32_t a;
    asm("{ .reg .u64 t; cvta.to.shared.u64 t, %1; cvt.u32.u64 %0, t; }"
        : "=r"(a) : "l"(p));
    return a;
}
__device__ __forceinline__ uint32_t pack_f16x2(float hi, float lo) {
    uint32_t r;
    asm("cvt.rn.f16x2.f32 %0, %1, %2;" : "=r"(r) : "f"(hi), "f"(lo));
    return r;
}
__device__ __forceinline__ uint32_t hmul2(uint32_t a, uint32_t b) {
    uint32_t r;
    asm("mul.rn.f16x2 %0, %1, %2;" : "=r"(r) : "r"(a), "r"(b));
    return r;
}
__device__ __forceinline__ void cp16(uint32_t dst, const void* src) {
    asm volatile("cp.async.cg.shared.global [%0], [%1], 16;"
                 :: "r"(dst), "l"(src) : "memory");
}
#define CP_COMMIT() asm volatile("cp.async.commit_group;" ::: "memory")
#define CP_WAIT(n)  asm volatile("cp.async.wait_group %0;" :: "n"(n) : "memory")

__device__ __forceinline__ void mma_f16(float* c, const uint32_t* a,
                                        uint32_t b0, uint32_t b1) {
    asm volatile(
        "mma.sync.aligned.m16n8k16.row.col.f32.f16.f16.f32 "
        "{%0,%1,%2,%3}, {%4,%5,%6,%7}, {%8,%9}, {%0,%1,%2,%3};"
        : "+f"(c[0]), "+f"(c[1]), "+f"(c[2]), "+f"(c[3])
        : "r"(a[0]), "r"(a[1]), "r"(a[2]), "r"(a[3]), "r"(b0), "r"(b1));
}

// ---- pack C -> fp16 pair-of-pairs layout; also zero the output ----
__global__ void __launch_bounds__(256) pack_c(const float* __restrict__ C,
                                              float* __restrict__ out) {
    unsigned idx = blockIdx.x * 256 + threadIdx.x;   // 524288 threads
    out[idx] = 0.f;                                  // out has 524288 floats
    int z = (int)(idx & 127);
    int q = (int)((idx >> 7) & 3);
    int c = (int)((idx >> 9) & 7);
    int i = (int)(idx >> 12);
    const float* base = C + ((size_t)i * DV + 16 * c + 2 * q) * DV + z;
    float v0 = base[0];
    float v1 = base[DV];
    float v8 = base[8 * DV];
    float v9 = base[9 * DV];
    uint2 r;
    r.x = pack_f16x2(v1, v0);
    r.y = pack_f16x2(v9, v8);
    g_CP[idx] = r;
}

__global__ void __launch_bounds__(NT, 1)
cooc_mma(const float* __restrict__ fa, float* __restrict__ out) {
    extern __shared__ uint2 smu[];
    const int tid  = threadIdx.x;
    const int warp = tid >> 5, lane = tid & 31;
    const int g = lane >> 2, q = lane & 3;
    const int mbase = (warp >> 1) * 32;   // warp-row tile (32 tokens)
    const int nbase = (warp & 1) * 64;    // warp-col tile (64 z)

    uint2* argp = smu + OFF_ARGP;
    uint32_t* arg32 = (uint32_t*)argp;
    const uint32_t sb = smem_u32(smu);

    // stream-K range for this CTA
    const unsigned nb = gridDim.x;
    const unsigned w0 = (unsigned)((unsigned long long)blockIdx.x * NWORK / nb);
    const unsigned w1 = (unsigned)((unsigned long long)(blockIdx.x + 1) * NWORK / nb);
    const unsigned n  = w1 - w0;

    // ---- arg restage: f32 LDG -> pair-packed half2 uint2 [t][c*4+q] ----
    auto stage_arg = [&](int tile) {
        const int tok0 = tile * 128;
        #pragma unroll 4
        for (int idx = tid; idx < 128 * 32; idx += NT) {
            int t = idx >> 5, c4 = idx & 31;
            float4 v = *(const float4*)(fa + (size_t)(tok0 + t) * 256 + DV + c4 * 4);
            int cc = c4 >> 2;            // chunk
            int ra = (2 * c4) & 7;       // r of first j2
            uint32_t w0v = pack_f16x2(v.y, v.x);
            uint32_t w1v = pack_f16x2(v.w, v.z);
            int ia = 2 * (t * ARGP_STRIDE + cc * 4 + (ra & 3)) + (ra >> 2);
            int rb = ra + 1;
            int ib = 2 * (t * ARGP_STRIDE + cc * 4 + (rb & 3)) + (rb >> 2);
            arg32[ia] = w0v;
            arg32[ib] = w1v;
        }
    };
    // ---- cp.async slab stager: g_CP[i] (32 rows x 128 uint2) -> stage stg ----
    auto stage_slab = [&](int i, int stg) {
        const uint2* src = g_CP + ((size_t)i << 12);
        uint32_t dstb = sb + (unsigned)stg * SLAB_U2 * 8;
        #pragma unroll
        for (int k = 0; k < 8; k++) {
            int c = tid + k * NT;          // 16B chunk id, 0..2047
            int row = c >> 6, col = c & 63;
            cp16(dstb + (row * SLAB_STRIDE + col * 2) * 8,
                 src + row * 128 + col * 2);
        }
    };
    // ---- func column prefetch for work unit w (4 regs) ----
    auto load_func = [&](unsigned w, float* fr) {
        const int tk = (int)(w >> 7) * 128;
        const int i  = (int)(w & 127);
        #pragma unroll
        for (int s = 0; s < 4; s++)
            fr[s] = fa[(size_t)(tk + mbase + g + 8 * s) * 256 + i];
    };

    float acc[2][8][4];
    #pragma unroll
    for (int mt = 0; mt < 2; mt++)
        #pragma unroll
        for (int nt = 0; nt < 8; nt++)
            #pragma unroll
            for (int k = 0; k < 4; k++) acc[mt][nt][k] = 0.f;

    auto flush = [&](int tile) {
        const int tok0 = tile * 128;
        #pragma unroll
        for (int mt = 0; mt < 2; mt++) {
            int r0 = tok0 + mbase + mt * 16 + g;
            #pragma unroll
            for (int nt = 0; nt < 8; nt++) {
                int col = nbase + nt * 8 + 2 * q;
                float* p0 = out + (size_t)r0 * DV + col;
                atomicAdd(p0,              acc[mt][nt][0]);
                atomicAdd(p0 + 1,          acc[mt][nt][1]);
                atomicAdd(p0 + 8 * DV,     acc[mt][nt][2]);
                atomicAdd(p0 + 8 * DV + 1, acc[mt][nt][3]);
                acc[mt][nt][0] = acc[mt][nt][1] = 0.f;
                acc[mt][nt][2] = acc[mt][nt][3] = 0.f;
            }
        }
    };

    int cur_tile = (int)(w0 >> 7);
    stage_arg(cur_tile);
    stage_slab((int)(w0 & 127), 0);
    if (n > 1) stage_slab((int)((w0 + 1) & 127), 1);
    CP_COMMIT();
    float fr_next[4];
    load_func(w0, fr_next);

    uint32_t aF[2][2][4];    // [buf][mt][frag]
    uint32_t bF[2][8][2];    // [buf][nt][frag]

    unsigned e = 0;
    int phase = 0;           // pair in use: stages {2*phase, 2*phase+1}
    while (e < n) {
        const unsigned ge = (n - e >= 2) ? 2u : 1u;   // group size
        const unsigned ne = e + ge;
        // prefetch next group into the other pair
        if (ne < n) {
            const int ps = 2 * (phase ^ 1);
            stage_slab((int)((w0 + ne) & 127), ps);
            if (ne + 1 < n) stage_slab((int)((w0 + ne + 1) & 127), ps + 1);
            CP_COMMIT();
        }
        if (ne < n) CP_WAIT(1); else CP_WAIT(0);
        __syncthreads();     // current pair (and argp on first group) visible

        for (unsigned k = 0; k < ge; k++) {
            const unsigned w = w0 + e + k;
            const int tile = (int)(w >> 7);
            if (tile != cur_tile) {      // uniform branch; <=1 per CTA
                flush(cur_tile);
                cur_tile = tile;
                __syncthreads();         // all warps done reading old argp
                stage_arg(cur_tile);
                __syncthreads();         // new argp visible
            }

            float fr_cur[4];
            #pragma unroll
            for (int s = 0; s < 4; s++) fr_cur[s] = fr_next[s];
            if (w + 1 < w1) load_func(w + 1, fr_next);

            const uint2* slab = smu + (unsigned)(2 * phase + (int)k) * SLAB_U2;

            uint32_t fr2[4];
            #pragma unroll
            for (int s = 0; s < 4; s++) fr2[s] = pack_f16x2(fr_cur[s], fr_cur[s]);

            // fragment loader for k16-chunk c into buffer fb (all LDS.64)
            auto load_chunk = [&](int c, int fb) {
                const uint2* brow = slab + (c * 4 + q) * SLAB_STRIDE + nbase + g;
                #pragma unroll
                for (int nt = 0; nt < 8; nt++) {
                    uint2 v = brow[nt * 8];
                    bF[fb][nt][0] = v.x;
                    bF[fb][nt][1] = v.y;
                }
                #pragma unroll
                for (int s = 0; s < 4; s++) {
                    uint2 av = argp[(mbase + g + 8 * s) * ARGP_STRIDE + c * 4 + q];
                    aF[fb][s >> 1][(s & 1) ? 1 : 0] = hmul2(fr2[s], av.x);
                    aF[fb][s >> 1][(s & 1) ? 3 : 2] = hmul2(fr2[s], av.y);
                }
            };

            load_chunk(0, 0);
            #pragma unroll
            for (int c = 0; c < 8; c++) {
                const int cur = c & 1, nxt = cur ^ 1;
                if (c < 7) load_chunk(c + 1, nxt);
                #pragma unroll
                for (int nt = 0; nt < 8; nt++) {
                    mma_f16(acc[0][nt], aF[cur][0], bF[cur][nt][0], bF[cur][nt][1]);
                    mma_f16(acc[1][nt], aF[cur][1], bF[cur][nt][0], bF[cur][nt][1]);
                }
            }
        }
        e = ne;
        phase ^= 1;
    }
    flush(cur_tile);
}

extern "C" void kernel_launch(void* const* d_in, const int* in_sizes, int n_in,
                              void* d_out, int out_size) {
    const float* fa = (const float*)d_in[0];   // (4,1024,256)
    const float* Cm = (const float*)d_in[1];   // (128,128,128)
    if (n_in >= 2 && in_sizes[0] > in_sizes[1]) {
        const float* t = fa; fa = Cm; Cm = t;
    }
    float* out = (float*)d_out;

    int nsm = 148;
    cudaDeviceGetAttribute(&nsm, cudaDevAttrMultiProcessorCount, 0);
    if (nsm <= 0 || nsm > NWORK) nsm = 148;

    cudaFuncSetAttribute(cooc_mma, cudaFuncAttributeMaxDynamicSharedMemorySize,
                         SM_BYTES);
    pack_c<<<2048, 256>>>(Cm, out);   // also zeroes out
    cooc_mma<<<nsm, NT, SM_BYTES>>>(fa, out);
}